// round 9
// baseline (speedup 1.0000x reference)
#include <cuda_runtime.h>
#include <cuda_bf16.h>

// Problem shapes (fixed by the reference setup_inputs)
#define B_DIM 64
#define S_DIM 512
#define H_DIM 768
#define W_DIM 256      // MAX_WORD_LEN
#define WE_DIM 300
#define OUT_H (H_DIM + WE_DIM)   // 1068

// first index i in [0, S) with a[i] >= key  (a sorted ascending)
__device__ __forceinline__ int lower_bound_512(const int* __restrict__ a, int key) {
    int lo = 0, hi = S_DIM;
    while (lo < hi) {                       // runs until interval length 0 (<=10 iters)
        int mid = (lo + hi) >> 1;
        if (__ldg(a + mid) < key) lo = mid + 1; else hi = mid;
    }
    return lo;
}

__global__ __launch_bounds__(256)
void embeddings_fused_kernel(const float* __restrict__ hidden,
                             const float* __restrict__ w2v,
                             const int*   __restrict__ token_ids,
                             const int*   __restrict__ word_ids,
                             float*       __restrict__ out) {
    const int w = blockIdx.x;   // word slot 0..255
    const int b = blockIdx.y;   // batch   0..63
    const int t = threadIdx.x;  // 0..255

    __shared__ int seg[2];      // [start, end)

    // Two threads compute the segment bounds once; broadcast via shared.
    if (t < 2) {
        const int* tok = token_ids + b * S_DIM;
        seg[t] = lower_bound_512(tok, w + t);
    }
    __syncthreads();

    float* __restrict__ orow = out + ((size_t)(b * W_DIM + w)) * OUT_H;

    if (t < H_DIM / 4) {
        // ---- segment mean of hidden rows whose token_id == w ----
        const int start = seg[0];
        const int end   = seg[1];

        float4 acc = make_float4(0.f, 0.f, 0.f, 0.f);
        const float* hptr = hidden + ((size_t)b * S_DIM + start) * H_DIM + t * 4;
        for (int i = start; i < end; ++i) {
            float4 v = *reinterpret_cast<const float4*>(hptr);
            acc.x += v.x; acc.y += v.y; acc.z += v.z; acc.w += v.w;
            hptr += H_DIM;
        }
        const int cnt = end - start;
        const float inv = (cnt > 0) ? (1.0f / (float)cnt) : 0.0f;
        acc.x *= inv; acc.y *= inv; acc.z *= inv; acc.w *= inv;
        reinterpret_cast<float4*>(orow)[t] = acc;
    } else {
        // ---- word2vec gather: out[b, w, 768:1068] = w2v[word_ids[b,w]] ----
        const int tt  = t - H_DIM / 4;                  // 0..63
        const int wid = __ldg(word_ids + b * W_DIM + w);
        const float4* __restrict__ src =
            reinterpret_cast<const float4*>(w2v + (size_t)wid * WE_DIM);
        float4* __restrict__ dst = reinterpret_cast<float4*>(orow + H_DIM);
        #pragma unroll
        for (int j = tt; j < WE_DIM / 4; j += 64)       // 75 float4 per row
            dst[j] = src[j];
    }
}

extern "C" void kernel_launch(void* const* d_in, const int* in_sizes, int n_in,
                              void* d_out, int out_size) {
    const float* hidden    = (const float*)d_in[0];
    const float* w2v       = (const float*)d_in[1];
    const int*   token_ids = (const int*)d_in[2];
    const int*   word_ids  = (const int*)d_in[3];
    float*       out       = (float*)d_out;

    dim3 grid(W_DIM, B_DIM);   // (256, 64) = 16384 blocks
    embeddings_fused_kernel<<<grid, 256>>>(hidden, w2v, token_ids, word_ids, out);
}

// round 11
// speedup vs baseline: 1.5165x; 1.5165x over previous
#include <cuda_runtime.h>
#include <cuda_bf16.h>

// Problem shapes (fixed by the reference setup_inputs)
#define B_DIM 64
#define S_DIM 512
#define H_DIM 768
#define W_DIM 256      // MAX_WORD_LEN
#define WE_DIM 300
#define OUT_H (H_DIM + WE_DIM)   // 1068

// Precomputed segment bounds: bounds[b][w] = first s with token_ids[b,s] >= w.
// bounds[b][W_DIM] == S_DIM. (__device__ global scratch: allocation-guard safe.)
__device__ int g_bounds[B_DIM][W_DIM + 1];

// ---------------------------------------------------------------------------
// Pass 1: per-batch smem-resident binary searches. 64 blocks x 256 threads.
// ---------------------------------------------------------------------------
__global__ __launch_bounds__(256)
void bounds_kernel(const int* __restrict__ token_ids) {
    __shared__ int tok[S_DIM];
    const int b = blockIdx.x;

    #pragma unroll
    for (int i = threadIdx.x; i < S_DIM; i += 256)
        tok[i] = __ldg(token_ids + b * S_DIM + i);
    __syncthreads();

    for (int w = threadIdx.x; w <= W_DIM; w += 256) {
        int lo = 0, hi = S_DIM;
        while (lo < hi) {                 // lower_bound in shared memory
            int mid = (lo + hi) >> 1;
            if (tok[mid] < w) lo = mid + 1; else hi = mid;
        }
        g_bounds[b][w] = lo;
    }
}

// ---------------------------------------------------------------------------
// Pass 2: segment mean + w2v gather. One block per (b, w). No search, no bar.
// ---------------------------------------------------------------------------
__global__ __launch_bounds__(256)
void embeddings_fused_kernel(const float* __restrict__ hidden,
                             const float* __restrict__ w2v,
                             const int*   __restrict__ word_ids,
                             float*       __restrict__ out) {
    const int w = blockIdx.x;   // word slot 0..255
    const int b = blockIdx.y;   // batch   0..63
    const int t = threadIdx.x;  // 0..255

    float* __restrict__ orow = out + ((size_t)(b * W_DIM + w)) * OUT_H;

    if (t < H_DIM / 4) {
        // ---- segment mean of hidden rows whose token_id == w ----
        const int start = __ldg(&g_bounds[b][w]);       // uniform across warp
        const int end   = __ldg(&g_bounds[b][w + 1]);

        float4 acc = make_float4(0.f, 0.f, 0.f, 0.f);
        const float* hptr = hidden + ((size_t)b * S_DIM + start) * H_DIM + t * 4;
        for (int i = start; i < end; ++i) {
            float4 v = *reinterpret_cast<const float4*>(hptr);
            acc.x += v.x; acc.y += v.y; acc.z += v.z; acc.w += v.w;
            hptr += H_DIM;
        }
        const int cnt = end - start;
        const float inv = (cnt > 0) ? (1.0f / (float)cnt) : 0.0f;
        acc.x *= inv; acc.y *= inv; acc.z *= inv; acc.w *= inv;
        reinterpret_cast<float4*>(orow)[t] = acc;
    } else {
        // ---- word2vec gather: out[b, w, 768:1068] = w2v[word_ids[b,w]] ----
        const int tt  = t - H_DIM / 4;                  // 0..63
        const int wid = __ldg(word_ids + b * W_DIM + w);
        const float4* __restrict__ src =
            reinterpret_cast<const float4*>(w2v + (size_t)wid * WE_DIM);
        float4* __restrict__ dst = reinterpret_cast<float4*>(orow + H_DIM);
        #pragma unroll
        for (int j = tt; j < WE_DIM / 4; j += 64)       // 75 float4 per row
            dst[j] = src[j];
    }
}

extern "C" void kernel_launch(void* const* d_in, const int* in_sizes, int n_in,
                              void* d_out, int out_size) {
    const float* hidden    = (const float*)d_in[0];
    const float* w2v       = (const float*)d_in[1];
    const int*   token_ids = (const int*)d_in[2];
    const int*   word_ids  = (const int*)d_in[3];
    float*       out       = (float*)d_out;

    bounds_kernel<<<B_DIM, 256>>>(token_ids);

    dim3 grid(W_DIM, B_DIM);   // (256, 64) = 16384 blocks
    embeddings_fused_kernel<<<grid, 256>>>(hidden, w2v, word_ids, out);
}